// round 12
// baseline (speedup 1.0000x reference)
#include <cuda_runtime.h>

#define N_B    64
#define T_LEN  2048
#define IN_D   8
#define C_CH   2
#define STEPS  2047
#define LCHUNK 8
#define NCHUNK 256           // 256*8 = 2048 >= 2047
#define WPB    4
#define NCHAIN (N_B * C_CH)          // 128
#define NJOBS  (NCHAIN * NCHUNK)     // 32768 chunk-jobs
#define NWARPS (NJOBS / 2)           // 16384 warps, 2 jobs each
#define FULLM  0xffffffffu

__device__ __align__(16) float g_part [NJOBS * 100];
__device__ __align__(16) float g_part2[NCHAIN * 16 * 100];

// ---------------------------------------------------------------------------
// Kernel 1: one warp per (chain, chunk-pair). Each warp advances TWO
// independent 8-step chunks (q and q+128) of the same chain, interleaved for
// ILP. Order-7 Taylor expm of skew G; tiles register-distributed
// (lane l<25 owns 2x2 tile (j2=l/5, k2=l%5)); exchanges via __shfl_sync.
// Steps past the chain end use dx=0 => E=I exactly (uniform trip count).
// 4096 blocks at 4 blocks/SM -> 6.92 waves (1.2% tail).
// ---------------------------------------------------------------------------
__global__ void __launch_bounds__(128) step_kernel(const float* __restrict__ x,
                                                   const float* __restrict__ A) {
    __shared__ float sk[C_CH * IN_D * 100];
    __shared__ float xs[WPB][2][(LCHUNK + 1) * IN_D];
    __shared__ __align__(16) float dxs[WPB][2][LCHUNK * IN_D];

    int tid = threadIdx.x;

    // skew = A - A^T
    for (int idx = tid; idx < C_CH * IN_D * 100; idx += 128) {
        int jk = idx % 100, ci = idx / 100;
        int j = jk / 10, k = jk % 10;
        sk[idx] = A[ci * 100 + j * 10 + k] - A[ci * 100 + k * 10 + j];
    }

    int warp = tid >> 5, lane = tid & 31;
    int w     = blockIdx.x * WPB + warp;     // [0, 16384)
    int q     = w & 127;                     // chunk pair: q and q+128
    int chain = w >> 7;
    int c     = chain & 1;
    int n     = chain >> 1;

    int t0j[2] = {q * LCHUNK, (q + 128) * LCHUNK};
    int nstepsj[2];
#pragma unroll
    for (int j = 0; j < 2; ++j) {
        nstepsj[j] = min(LCHUNK, STEPS - t0j[j]);
        const float* xp = x + ((size_t)n * T_LEN + t0j[j]) * IN_D;
        float* xw = xs[warp][j];
        int cnt = (nstepsj[j] + 1) * IN_D;
        for (int idx = lane; idx < cnt; idx += 32) xw[idx] = xp[idx];
    }
    __syncthreads();                          // sk + xw ready

#pragma unroll
    for (int j = 0; j < 2; ++j) {
        const float* xw = xs[warp][j];
        float* dxp = dxs[warp][j];
        int lim = nstepsj[j] * IN_D;
        for (int idx = lane; idx < LCHUNK * IN_D; idx += 32)
            dxp[idx] = (idx < lim) ? (xw[idx + IN_D] - xw[idx]) : 0.f;
    }
    __syncwarp();

    bool act = lane < 25;
    int l  = act ? lane : 24;
    int j2 = l / 5, k2 = l % 5;
    int r0 = 2 * j2, c0 = 2 * k2;
    float dI = (j2 == k2) ? 1.f : 0.f;

    // skew tiles -> registers (shared by both jobs: same chain/channel)
    const float* skc = sk + c * IN_D * 100;
    float ska[IN_D][4];
#pragma unroll
    for (int i = 0; i < IN_D; ++i) {
        float2 a0 = *(const float2*)(skc + i * 100 + r0 * 10 + c0);
        float2 a1 = *(const float2*)(skc + i * 100 + r0 * 10 + 10 + c0);
        ska[i][0] = a0.x; ska[i][1] = a0.y; ska[i][2] = a1.x; ska[i][3] = a1.y;
    }

    const float c2 = 0.5f,      c4 = 1.f / 24.f,  c6 = 1.f / 720.f;
    const float s2 = 1.f / 6.f, s4 = 1.f / 120.f, s6 = 1.f / 5040.f;

    float ac00[2], ac01[2], ac10[2], ac11[2];
#pragma unroll
    for (int j = 0; j < 2; ++j) { ac00[j] = dI; ac01[j] = 0.f; ac10[j] = 0.f; ac11[j] = dI; }

    float Gr0[2][10], Gr1[2][10], Wr0[2][10], Wr1[2][10];
    float g00[2], g01[2], g10[2], g11[2];
    float w00[2], w01[2], w10[2], w11[2];
    float C00[2], C01[2], C10[2], C11[2];
    float S00[2], S01[2], S10[2], S11[2];
    float e00[2], e01[2], e10[2], e11[2];

    for (int t = 0; t < LCHUNK; ++t) {
        // ---- G tiles ----
#pragma unroll
        for (int j = 0; j < 2; ++j) {
            const float* d = dxs[warp][j] + t * IN_D;
            float4 dA4 = *(const float4*)(d);
            float4 dB4 = *(const float4*)(d + 4);
            float dv[8] = {dA4.x, dA4.y, dA4.z, dA4.w, dB4.x, dB4.y, dB4.z, dB4.w};
            float a = 0.f, b = 0.f, cc = 0.f, dd = 0.f;
#pragma unroll
            for (int i = 0; i < 8; ++i) {
                a = fmaf(dv[i], ska[i][0], a); b  = fmaf(dv[i], ska[i][1], b);
                cc = fmaf(dv[i], ska[i][2], cc); dd = fmaf(dv[i], ska[i][3], dd);
            }
            g00[j] = a; g01[j] = b; g10[j] = cc; g11[j] = dd;
        }

        // ---- G strips ----
#pragma unroll
        for (int j = 0; j < 2; ++j)
#pragma unroll
            for (int k = 0; k < 5; ++k) {
                int src = j2 * 5 + k;
                Gr0[j][2*k]   = __shfl_sync(FULLM, g00[j], src);
                Gr0[j][2*k+1] = __shfl_sync(FULLM, g01[j], src);
                Gr1[j][2*k]   = __shfl_sync(FULLM, g10[j], src);
                Gr1[j][2*k+1] = __shfl_sync(FULLM, g11[j], src);
            }

        // ---- W = G@G ----
#pragma unroll
        for (int j = 0; j < 2; ++j) {
            float o00 = 0.f, o01 = 0.f, o10 = 0.f, o11 = 0.f;
#pragma unroll
            for (int i = 0; i < 5; ++i) {
                int src = i * 5 + k2;
                float b00 = __shfl_sync(FULLM, g00[j], src);
                float b01 = __shfl_sync(FULLM, g01[j], src);
                float b10 = __shfl_sync(FULLM, g10[j], src);
                float b11 = __shfl_sync(FULLM, g11[j], src);
                float a00 = Gr0[j][2*i], a01 = Gr0[j][2*i+1];
                float a10 = Gr1[j][2*i], a11 = Gr1[j][2*i+1];
                o00 = fmaf(a00, b00, o00); o00 = fmaf(a01, b10, o00);
                o01 = fmaf(a00, b01, o01); o01 = fmaf(a01, b11, o01);
                o10 = fmaf(a10, b00, o10); o10 = fmaf(a11, b10, o10);
                o11 = fmaf(a10, b01, o11); o11 = fmaf(a11, b11, o11);
            }
            w00[j] = o00; w01[j] = o01; w10[j] = o10; w11[j] = o11;
        }

        // ---- W strips ----
#pragma unroll
        for (int j = 0; j < 2; ++j)
#pragma unroll
            for (int k = 0; k < 5; ++k) {
                int src = j2 * 5 + k;
                Wr0[j][2*k]   = __shfl_sync(FULLM, w00[j], src);
                Wr0[j][2*k+1] = __shfl_sync(FULLM, w01[j], src);
                Wr1[j][2*k]   = __shfl_sync(FULLM, w10[j], src);
                Wr1[j][2*k+1] = __shfl_sync(FULLM, w11[j], src);
            }

        // ---- P = W@W ; C,S low-order folds ----
#pragma unroll
        for (int j = 0; j < 2; ++j) {
            float o00 = 0.f, o01 = 0.f, o10 = 0.f, o11 = 0.f;
#pragma unroll
            for (int i = 0; i < 5; ++i) {
                int src = i * 5 + k2;
                float b00 = __shfl_sync(FULLM, w00[j], src);
                float b01 = __shfl_sync(FULLM, w01[j], src);
                float b10 = __shfl_sync(FULLM, w10[j], src);
                float b11 = __shfl_sync(FULLM, w11[j], src);
                float a00 = Wr0[j][2*i], a01 = Wr0[j][2*i+1];
                float a10 = Wr1[j][2*i], a11 = Wr1[j][2*i+1];
                o00 = fmaf(a00, b00, o00); o00 = fmaf(a01, b10, o00);
                o01 = fmaf(a00, b01, o01); o01 = fmaf(a01, b11, o01);
                o10 = fmaf(a10, b00, o10); o10 = fmaf(a11, b10, o10);
                o11 = fmaf(a10, b01, o11); o11 = fmaf(a11, b11, o11);
            }
            C00[j] = fmaf(c4, o00, fmaf(c2, w00[j], dI));
            C01[j] = fmaf(c4, o01, c2 * w01[j]);
            C10[j] = fmaf(c4, o10, c2 * w10[j]);
            C11[j] = fmaf(c4, o11, fmaf(c2, w11[j], dI));
            S00[j] = fmaf(s4, o00, fmaf(s2, w00[j], dI));
            S01[j] = fmaf(s4, o01, s2 * w01[j]);
            S10[j] = fmaf(s4, o10, s2 * w10[j]);
            S11[j] = fmaf(s4, o11, fmaf(s2, w11[j], dI));
            // reuse g-regs to carry P tile for the V6 gather
            g00[j] = o00; g01[j] = o01; g10[j] = o10; g11[j] = o11;
        }

        // ---- V6 = W@P ; fold into C,S ----
#pragma unroll
        for (int j = 0; j < 2; ++j) {
            float o00 = 0.f, o01 = 0.f, o10 = 0.f, o11 = 0.f;
#pragma unroll
            for (int i = 0; i < 5; ++i) {
                int src = i * 5 + k2;
                float b00 = __shfl_sync(FULLM, g00[j], src);
                float b01 = __shfl_sync(FULLM, g01[j], src);
                float b10 = __shfl_sync(FULLM, g10[j], src);
                float b11 = __shfl_sync(FULLM, g11[j], src);
                float a00 = Wr0[j][2*i], a01 = Wr0[j][2*i+1];
                float a10 = Wr1[j][2*i], a11 = Wr1[j][2*i+1];
                o00 = fmaf(a00, b00, o00); o00 = fmaf(a01, b10, o00);
                o01 = fmaf(a00, b01, o01); o01 = fmaf(a01, b11, o01);
                o10 = fmaf(a10, b00, o10); o10 = fmaf(a11, b10, o10);
                o11 = fmaf(a10, b01, o11); o11 = fmaf(a11, b11, o11);
            }
            C00[j] = fmaf(c6, o00, C00[j]); C01[j] = fmaf(c6, o01, C01[j]);
            C10[j] = fmaf(c6, o10, C10[j]); C11[j] = fmaf(c6, o11, C11[j]);
            S00[j] = fmaf(s6, o00, S00[j]); S01[j] = fmaf(s6, o01, S01[j]);
            S10[j] = fmaf(s6, o10, S10[j]); S11[j] = fmaf(s6, o11, S11[j]);
        }

        // ---- E = C + G@S ----
#pragma unroll
        for (int j = 0; j < 2; ++j) {
            float o00 = C00[j], o01 = C01[j], o10 = C10[j], o11 = C11[j];
#pragma unroll
            for (int i = 0; i < 5; ++i) {
                int src = i * 5 + k2;
                float b00 = __shfl_sync(FULLM, S00[j], src);
                float b01 = __shfl_sync(FULLM, S01[j], src);
                float b10 = __shfl_sync(FULLM, S10[j], src);
                float b11 = __shfl_sync(FULLM, S11[j], src);
                float a00 = Gr0[j][2*i], a01 = Gr0[j][2*i+1];
                float a10 = Gr1[j][2*i], a11 = Gr1[j][2*i+1];
                o00 = fmaf(a00, b00, o00); o00 = fmaf(a01, b10, o00);
                o01 = fmaf(a00, b01, o01); o01 = fmaf(a01, b11, o01);
                o10 = fmaf(a10, b00, o10); o10 = fmaf(a11, b10, o10);
                o11 = fmaf(a10, b01, o11); o11 = fmaf(a11, b11, o11);
            }
            e00[j] = o00; e01[j] = o01; e10[j] = o10; e11[j] = o11;
        }

        // ---- Acc = Acc @ E ----
#pragma unroll
        for (int j = 0; j < 2; ++j) {
            float o00 = 0.f, o01 = 0.f, o10 = 0.f, o11 = 0.f;
#pragma unroll
            for (int i = 0; i < 5; ++i) {
                int sa = j2 * 5 + i;
                int sb = i * 5 + k2;
                float a00 = __shfl_sync(FULLM, ac00[j], sa);
                float a01 = __shfl_sync(FULLM, ac01[j], sa);
                float a10 = __shfl_sync(FULLM, ac10[j], sa);
                float a11 = __shfl_sync(FULLM, ac11[j], sa);
                float b00 = __shfl_sync(FULLM, e00[j], sb);
                float b01 = __shfl_sync(FULLM, e01[j], sb);
                float b10 = __shfl_sync(FULLM, e10[j], sb);
                float b11 = __shfl_sync(FULLM, e11[j], sb);
                o00 = fmaf(a00, b00, o00); o00 = fmaf(a01, b10, o00);
                o01 = fmaf(a00, b01, o01); o01 = fmaf(a01, b11, o01);
                o10 = fmaf(a10, b00, o10); o10 = fmaf(a11, b10, o10);
                o11 = fmaf(a10, b01, o11); o11 = fmaf(a11, b11, o11);
            }
            ac00[j] = o00; ac01[j] = o01; ac10[j] = o10; ac11[j] = o11;
        }
    }

    if (act) {
#pragma unroll
        for (int j = 0; j < 2; ++j) {
            float* pp = g_part + (size_t)(chain * NCHUNK + q + j * 128) * 100;
            *(float2*)(pp + r0 * 10 + c0)       = make_float2(ac00[j], ac01[j]);
            *(float2*)(pp + (r0 + 1) * 10 + c0) = make_float2(ac10[j], ac11[j]);
        }
    }
}

// ---------------------------------------------------------------------------
// Tree combine, shuffle-register version with global-load prefetch.
// Acc and P tiles live in registers; no smem, no __syncwarp.
// ---------------------------------------------------------------------------
__device__ __forceinline__ void combine_run_reg(const float* __restrict__ src,
                                                float* __restrict__ dst,
                                                int lane, int cntp) {
    bool act = lane < 25;
    int l  = act ? lane : 24;
    int j2 = l / 5, k2 = l % 5;
    int r0 = 2 * j2, c0 = 2 * k2;

    // Acc = first partial's tile
    float2 a0 = *(const float2*)(src + r0 * 10 + c0);
    float2 a1 = *(const float2*)(src + (r0 + 1) * 10 + c0);
    float ac00 = a0.x, ac01 = a0.y, ac10 = a1.x, ac11 = a1.y;

    // prefetch p=1 tile
    float2 p0 = *(const float2*)(src + 100 + r0 * 10 + c0);
    float2 p1 = *(const float2*)(src + 100 + (r0 + 1) * 10 + c0);

    for (int p = 1; p < cntp; ++p) {
        float bc00 = p0.x, bc01 = p0.y, bc10 = p1.x, bc11 = p1.y;
        if (p + 1 < cntp) {                      // prefetch next (overlaps matmul)
            p0 = *(const float2*)(src + (p + 1) * 100 + r0 * 10 + c0);
            p1 = *(const float2*)(src + (p + 1) * 100 + (r0 + 1) * 10 + c0);
        }
        float o00 = 0.f, o01 = 0.f, o10 = 0.f, o11 = 0.f;
#pragma unroll
        for (int i = 0; i < 5; ++i) {
            int sa = j2 * 5 + i;
            int sb = i * 5 + k2;
            float a00 = __shfl_sync(FULLM, ac00, sa);
            float a01 = __shfl_sync(FULLM, ac01, sa);
            float a10 = __shfl_sync(FULLM, ac10, sa);
            float a11 = __shfl_sync(FULLM, ac11, sa);
            float b00 = __shfl_sync(FULLM, bc00, sb);
            float b01 = __shfl_sync(FULLM, bc01, sb);
            float b10 = __shfl_sync(FULLM, bc10, sb);
            float b11 = __shfl_sync(FULLM, bc11, sb);
            o00 = fmaf(a00, b00, o00); o00 = fmaf(a01, b10, o00);
            o01 = fmaf(a00, b01, o01); o01 = fmaf(a01, b11, o01);
            o10 = fmaf(a10, b00, o10); o10 = fmaf(a11, b10, o10);
            o11 = fmaf(a10, b01, o11); o11 = fmaf(a11, b11, o11);
        }
        ac00 = o00; ac01 = o01; ac10 = o10; ac11 = o11;
    }

    if (act) {
        *(float2*)(dst + r0 * 10 + c0)       = make_float2(ac00, ac01);
        *(float2*)(dst + (r0 + 1) * 10 + c0) = make_float2(ac10, ac11);
    }
}

__global__ void __launch_bounds__(128) combineA() {
    int warp = threadIdx.x >> 5, lane = threadIdx.x & 31;
    int w = blockIdx.x * WPB + warp;          // [0, 2048)
    int chain = w >> 4, g = w & 15;
    combine_run_reg(g_part + ((size_t)chain * NCHUNK + g * 16) * 100,
                    g_part2 + ((size_t)chain * 16 + g) * 100,
                    lane, 16);
}

__global__ void __launch_bounds__(128) combineB(float* __restrict__ out) {
    int warp = threadIdx.x >> 5, lane = threadIdx.x & 31;
    int chain = blockIdx.x * WPB + warp;      // [0, 128)
    combine_run_reg(g_part2 + (size_t)chain * 16 * 100,
                    out + (size_t)chain * 100,
                    lane, 16);
}

extern "C" void kernel_launch(void* const* d_in, const int* in_sizes, int n_in,
                              void* d_out, int out_size) {
    const float* x = (const float*)d_in[0];
    const float* A = (const float*)d_in[1];
    if (n_in >= 2 && in_sizes[0] < in_sizes[1]) {
        const float* t = x; x = A; A = t;
    }

    step_kernel<<<NWARPS / WPB, 128>>>(x, A);   // 4096 blocks
    combineA<<<2048 / WPB, 128>>>();            // 512 blocks
    combineB<<<128 / WPB, 128>>>((float*)d_out);// 32 blocks
}

// round 13
// speedup vs baseline: 1.0360x; 1.0360x over previous
#include <cuda_runtime.h>

#define N_B    64
#define T_LEN  2048
#define IN_D   8
#define C_CH   2
#define STEPS  2047
#define LCHUNK 8
#define NCHUNK 256           // 256*8 = 2048 >= 2047
#define WPB    4
#define NCHAIN (N_B * C_CH)          // 128
#define NPAIR  (NCHUNK / 2)          // 128 merged partials per chain
#define NWARPS (NCHAIN * NPAIR)      // 16384 warps, 2 adjacent chunks each
#define FULLM  0xffffffffu

__device__ __align__(16) float g_part[NCHAIN * NPAIR * 100];

// ---------------------------------------------------------------------------
// Kernel 1: one warp per (chain, chunk-pair). Each warp advances TWO ADJACENT
// 8-step chunks (2q, 2q+1), interleaved for ILP, then merges them in-register
// and writes one 16-step partial. Order-7 Taylor expm of skew G; tiles
// register-distributed (lane l<25 owns 2x2 tile (j2=l/5, k2=l%5)); exchanges
// via __shfl_sync. Steps past chain end use dx=0 => E=I exactly.
// ---------------------------------------------------------------------------
__global__ void __launch_bounds__(128) step_kernel(const float* __restrict__ x,
                                                   const float* __restrict__ A) {
    __shared__ float sk[C_CH * IN_D * 100];
    __shared__ float xs[WPB][2][(LCHUNK + 1) * IN_D];
    __shared__ __align__(16) float dxs[WPB][2][LCHUNK * IN_D];

    int tid = threadIdx.x;

    // skew = A - A^T
    for (int idx = tid; idx < C_CH * IN_D * 100; idx += 128) {
        int jk = idx % 100, ci = idx / 100;
        int j = jk / 10, k = jk % 10;
        sk[idx] = A[ci * 100 + j * 10 + k] - A[ci * 100 + k * 10 + j];
    }

    int warp = tid >> 5, lane = tid & 31;
    int w     = blockIdx.x * WPB + warp;     // [0, 16384)
    int q     = w & (NPAIR - 1);             // pair index
    int chain = w >> 7;
    int c     = chain & 1;
    int n     = chain >> 1;

    int t0j[2] = {(2 * q) * LCHUNK, (2 * q + 1) * LCHUNK};
    int nstepsj[2];
#pragma unroll
    for (int j = 0; j < 2; ++j) {
        nstepsj[j] = max(0, min(LCHUNK, STEPS - t0j[j]));
        const float* xp = x + ((size_t)n * T_LEN + t0j[j]) * IN_D;
        float* xw = xs[warp][j];
        int cnt = (nstepsj[j] + 1) * IN_D;
        for (int idx = lane; idx < cnt; idx += 32) xw[idx] = xp[idx];
    }
    __syncthreads();                          // sk + xw ready

#pragma unroll
    for (int j = 0; j < 2; ++j) {
        const float* xw = xs[warp][j];
        float* dxp = dxs[warp][j];
        int lim = nstepsj[j] * IN_D;
        for (int idx = lane; idx < LCHUNK * IN_D; idx += 32)
            dxp[idx] = (idx < lim) ? (xw[idx + IN_D] - xw[idx]) : 0.f;
    }
    __syncwarp();

    bool act = lane < 25;
    int l  = act ? lane : 24;
    int j2 = l / 5, k2 = l % 5;
    int r0 = 2 * j2, c0 = 2 * k2;
    float dI = (j2 == k2) ? 1.f : 0.f;

    // skew tiles -> registers (shared by both jobs: same chain/channel)
    const float* skc = sk + c * IN_D * 100;
    float ska[IN_D][4];
#pragma unroll
    for (int i = 0; i < IN_D; ++i) {
        float2 a0 = *(const float2*)(skc + i * 100 + r0 * 10 + c0);
        float2 a1 = *(const float2*)(skc + i * 100 + r0 * 10 + 10 + c0);
        ska[i][0] = a0.x; ska[i][1] = a0.y; ska[i][2] = a1.x; ska[i][3] = a1.y;
    }

    const float c2 = 0.5f,      c4 = 1.f / 24.f,  c6 = 1.f / 720.f;
    const float s2 = 1.f / 6.f, s4 = 1.f / 120.f, s6 = 1.f / 5040.f;

    float ac00[2], ac01[2], ac10[2], ac11[2];
#pragma unroll
    for (int j = 0; j < 2; ++j) { ac00[j] = dI; ac01[j] = 0.f; ac10[j] = 0.f; ac11[j] = dI; }

    float Gr0[2][10], Gr1[2][10], Wr0[2][10], Wr1[2][10];
    float g00[2], g01[2], g10[2], g11[2];
    float w00[2], w01[2], w10[2], w11[2];
    float C00[2], C01[2], C10[2], C11[2];
    float S00[2], S01[2], S10[2], S11[2];
    float e00[2], e01[2], e10[2], e11[2];

    for (int t = 0; t < LCHUNK; ++t) {
        // ---- G tiles ----
#pragma unroll
        for (int j = 0; j < 2; ++j) {
            const float* d = dxs[warp][j] + t * IN_D;
            float4 dA4 = *(const float4*)(d);
            float4 dB4 = *(const float4*)(d + 4);
            float dv[8] = {dA4.x, dA4.y, dA4.z, dA4.w, dB4.x, dB4.y, dB4.z, dB4.w};
            float a = 0.f, b = 0.f, cc = 0.f, dd = 0.f;
#pragma unroll
            for (int i = 0; i < 8; ++i) {
                a = fmaf(dv[i], ska[i][0], a); b  = fmaf(dv[i], ska[i][1], b);
                cc = fmaf(dv[i], ska[i][2], cc); dd = fmaf(dv[i], ska[i][3], dd);
            }
            g00[j] = a; g01[j] = b; g10[j] = cc; g11[j] = dd;
        }

        // ---- G strips ----
#pragma unroll
        for (int j = 0; j < 2; ++j)
#pragma unroll
            for (int k = 0; k < 5; ++k) {
                int src = j2 * 5 + k;
                Gr0[j][2*k]   = __shfl_sync(FULLM, g00[j], src);
                Gr0[j][2*k+1] = __shfl_sync(FULLM, g01[j], src);
                Gr1[j][2*k]   = __shfl_sync(FULLM, g10[j], src);
                Gr1[j][2*k+1] = __shfl_sync(FULLM, g11[j], src);
            }

        // ---- W = G@G ----
#pragma unroll
        for (int j = 0; j < 2; ++j) {
            float o00 = 0.f, o01 = 0.f, o10 = 0.f, o11 = 0.f;
#pragma unroll
            for (int i = 0; i < 5; ++i) {
                int src = i * 5 + k2;
                float b00 = __shfl_sync(FULLM, g00[j], src);
                float b01 = __shfl_sync(FULLM, g01[j], src);
                float b10 = __shfl_sync(FULLM, g10[j], src);
                float b11 = __shfl_sync(FULLM, g11[j], src);
                float a00 = Gr0[j][2*i], a01 = Gr0[j][2*i+1];
                float a10 = Gr1[j][2*i], a11 = Gr1[j][2*i+1];
                o00 = fmaf(a00, b00, o00); o00 = fmaf(a01, b10, o00);
                o01 = fmaf(a00, b01, o01); o01 = fmaf(a01, b11, o01);
                o10 = fmaf(a10, b00, o10); o10 = fmaf(a11, b10, o10);
                o11 = fmaf(a10, b01, o11); o11 = fmaf(a11, b11, o11);
            }
            w00[j] = o00; w01[j] = o01; w10[j] = o10; w11[j] = o11;
        }

        // ---- W strips ----
#pragma unroll
        for (int j = 0; j < 2; ++j)
#pragma unroll
            for (int k = 0; k < 5; ++k) {
                int src = j2 * 5 + k;
                Wr0[j][2*k]   = __shfl_sync(FULLM, w00[j], src);
                Wr0[j][2*k+1] = __shfl_sync(FULLM, w01[j], src);
                Wr1[j][2*k]   = __shfl_sync(FULLM, w10[j], src);
                Wr1[j][2*k+1] = __shfl_sync(FULLM, w11[j], src);
            }

        // ---- P = W@W ; C,S low-order folds ----
#pragma unroll
        for (int j = 0; j < 2; ++j) {
            float o00 = 0.f, o01 = 0.f, o10 = 0.f, o11 = 0.f;
#pragma unroll
            for (int i = 0; i < 5; ++i) {
                int src = i * 5 + k2;
                float b00 = __shfl_sync(FULLM, w00[j], src);
                float b01 = __shfl_sync(FULLM, w01[j], src);
                float b10 = __shfl_sync(FULLM, w10[j], src);
                float b11 = __shfl_sync(FULLM, w11[j], src);
                float a00 = Wr0[j][2*i], a01 = Wr0[j][2*i+1];
                float a10 = Wr1[j][2*i], a11 = Wr1[j][2*i+1];
                o00 = fmaf(a00, b00, o00); o00 = fmaf(a01, b10, o00);
                o01 = fmaf(a00, b01, o01); o01 = fmaf(a01, b11, o01);
                o10 = fmaf(a10, b00, o10); o10 = fmaf(a11, b10, o10);
                o11 = fmaf(a10, b01, o11); o11 = fmaf(a11, b11, o11);
            }
            C00[j] = fmaf(c4, o00, fmaf(c2, w00[j], dI));
            C01[j] = fmaf(c4, o01, c2 * w01[j]);
            C10[j] = fmaf(c4, o10, c2 * w10[j]);
            C11[j] = fmaf(c4, o11, fmaf(c2, w11[j], dI));
            S00[j] = fmaf(s4, o00, fmaf(s2, w00[j], dI));
            S01[j] = fmaf(s4, o01, s2 * w01[j]);
            S10[j] = fmaf(s4, o10, s2 * w10[j]);
            S11[j] = fmaf(s4, o11, fmaf(s2, w11[j], dI));
            // reuse g-regs to carry P tile for the V6 gather
            g00[j] = o00; g01[j] = o01; g10[j] = o10; g11[j] = o11;
        }

        // ---- V6 = W@P ; fold into C,S ----
#pragma unroll
        for (int j = 0; j < 2; ++j) {
            float o00 = 0.f, o01 = 0.f, o10 = 0.f, o11 = 0.f;
#pragma unroll
            for (int i = 0; i < 5; ++i) {
                int src = i * 5 + k2;
                float b00 = __shfl_sync(FULLM, g00[j], src);
                float b01 = __shfl_sync(FULLM, g01[j], src);
                float b10 = __shfl_sync(FULLM, g10[j], src);
                float b11 = __shfl_sync(FULLM, g11[j], src);
                float a00 = Wr0[j][2*i], a01 = Wr0[j][2*i+1];
                float a10 = Wr1[j][2*i], a11 = Wr1[j][2*i+1];
                o00 = fmaf(a00, b00, o00); o00 = fmaf(a01, b10, o00);
                o01 = fmaf(a00, b01, o01); o01 = fmaf(a01, b11, o01);
                o10 = fmaf(a10, b00, o10); o10 = fmaf(a11, b10, o10);
                o11 = fmaf(a10, b01, o11); o11 = fmaf(a11, b11, o11);
            }
            C00[j] = fmaf(c6, o00, C00[j]); C01[j] = fmaf(c6, o01, C01[j]);
            C10[j] = fmaf(c6, o10, C10[j]); C11[j] = fmaf(c6, o11, C11[j]);
            S00[j] = fmaf(s6, o00, S00[j]); S01[j] = fmaf(s6, o01, S01[j]);
            S10[j] = fmaf(s6, o10, S10[j]); S11[j] = fmaf(s6, o11, S11[j]);
        }

        // ---- E = C + G@S ----
#pragma unroll
        for (int j = 0; j < 2; ++j) {
            float o00 = C00[j], o01 = C01[j], o10 = C10[j], o11 = C11[j];
#pragma unroll
            for (int i = 0; i < 5; ++i) {
                int src = i * 5 + k2;
                float b00 = __shfl_sync(FULLM, S00[j], src);
                float b01 = __shfl_sync(FULLM, S01[j], src);
                float b10 = __shfl_sync(FULLM, S10[j], src);
                float b11 = __shfl_sync(FULLM, S11[j], src);
                float a00 = Gr0[j][2*i], a01 = Gr0[j][2*i+1];
                float a10 = Gr1[j][2*i], a11 = Gr1[j][2*i+1];
                o00 = fmaf(a00, b00, o00); o00 = fmaf(a01, b10, o00);
                o01 = fmaf(a00, b01, o01); o01 = fmaf(a01, b11, o01);
                o10 = fmaf(a10, b00, o10); o10 = fmaf(a11, b10, o10);
                o11 = fmaf(a10, b01, o11); o11 = fmaf(a11, b11, o11);
            }
            e00[j] = o00; e01[j] = o01; e10[j] = o10; e11[j] = o11;
        }

        // ---- Acc = Acc @ E ----
#pragma unroll
        for (int j = 0; j < 2; ++j) {
            float o00 = 0.f, o01 = 0.f, o10 = 0.f, o11 = 0.f;
#pragma unroll
            for (int i = 0; i < 5; ++i) {
                int sa = j2 * 5 + i;
                int sb = i * 5 + k2;
                float a00 = __shfl_sync(FULLM, ac00[j], sa);
                float a01 = __shfl_sync(FULLM, ac01[j], sa);
                float a10 = __shfl_sync(FULLM, ac10[j], sa);
                float a11 = __shfl_sync(FULLM, ac11[j], sa);
                float b00 = __shfl_sync(FULLM, e00[j], sb);
                float b01 = __shfl_sync(FULLM, e01[j], sb);
                float b10 = __shfl_sync(FULLM, e10[j], sb);
                float b11 = __shfl_sync(FULLM, e11[j], sb);
                o00 = fmaf(a00, b00, o00); o00 = fmaf(a01, b10, o00);
                o01 = fmaf(a00, b01, o01); o01 = fmaf(a01, b11, o01);
                o10 = fmaf(a10, b00, o10); o10 = fmaf(a11, b10, o10);
                o11 = fmaf(a10, b01, o11); o11 = fmaf(a11, b11, o11);
            }
            ac00[j] = o00; ac01[j] = o01; ac10[j] = o10; ac11[j] = o11;
        }
    }

    // ---- merge the adjacent pair: M = Acc0 @ Acc1 (time order) ----
    {
        float o00 = 0.f, o01 = 0.f, o10 = 0.f, o11 = 0.f;
#pragma unroll
        for (int i = 0; i < 5; ++i) {
            int sa = j2 * 5 + i;
            int sb = i * 5 + k2;
            float a00 = __shfl_sync(FULLM, ac00[0], sa);
            float a01 = __shfl_sync(FULLM, ac01[0], sa);
            float a10 = __shfl_sync(FULLM, ac10[0], sa);
            float a11 = __shfl_sync(FULLM, ac11[0], sa);
            float b00 = __shfl_sync(FULLM, ac00[1], sb);
            float b01 = __shfl_sync(FULLM, ac01[1], sb);
            float b10 = __shfl_sync(FULLM, ac10[1], sb);
            float b11 = __shfl_sync(FULLM, ac11[1], sb);
            o00 = fmaf(a00, b00, o00); o00 = fmaf(a01, b10, o00);
            o01 = fmaf(a00, b01, o01); o01 = fmaf(a01, b11, o01);
            o10 = fmaf(a10, b00, o10); o10 = fmaf(a11, b10, o10);
            o11 = fmaf(a10, b01, o11); o11 = fmaf(a11, b11, o11);
        }
        if (act) {
            float* pp = g_part + (size_t)(chain * NPAIR + q) * 100;
            *(float2*)(pp + r0 * 10 + c0)       = make_float2(o00, o01);
            *(float2*)(pp + (r0 + 1) * 10 + c0) = make_float2(o10, o11);
        }
    }
}

// ---------------------------------------------------------------------------
// Single combine kernel: one block per chain (128 blocks x 128 threads).
// Each warp serially reduces 32 partials via register-shuffle matmuls with
// 2-deep prefetch; warp results merged via smem by warp 0.
// ---------------------------------------------------------------------------
__global__ void __launch_bounds__(128) combine_kernel(float* __restrict__ out) {
    __shared__ __align__(16) float wres[4][100];
    __shared__ __align__(16) float wk[2][100];

    int chain = blockIdx.x;
    int warp = threadIdx.x >> 5, lane = threadIdx.x & 31;
    bool act = lane < 25;
    int l  = act ? lane : 24;
    int j2 = l / 5, k2 = l % 5;
    int r0 = 2 * j2, c0 = 2 * k2;

    const float* src = g_part + ((size_t)chain * NPAIR + warp * 32) * 100;

    // Acc = partial 0
    float2 a0 = *(const float2*)(src + r0 * 10 + c0);
    float2 a1 = *(const float2*)(src + (r0 + 1) * 10 + c0);
    float ac00 = a0.x, ac01 = a0.y, ac10 = a1.x, ac11 = a1.y;

    // 2-deep prefetch ring
    float2 pf0[2], pf1[2];
#pragma unroll
    for (int d = 0; d < 2; ++d) {
        pf0[d] = *(const float2*)(src + (1 + d) * 100 + r0 * 10 + c0);
        pf1[d] = *(const float2*)(src + (1 + d) * 100 + (r0 + 1) * 10 + c0);
    }

    for (int p = 1; p < 32; ++p) {
        float bc00 = pf0[(p - 1) & 1].x, bc01 = pf0[(p - 1) & 1].y;
        float bc10 = pf1[(p - 1) & 1].x, bc11 = pf1[(p - 1) & 1].y;
        if (p + 2 < 32) {
            pf0[(p + 1) & 1] = *(const float2*)(src + (p + 2) * 100 + r0 * 10 + c0);
            pf1[(p + 1) & 1] = *(const float2*)(src + (p + 2) * 100 + (r0 + 1) * 10 + c0);
        }
        float o00 = 0.f, o01 = 0.f, o10 = 0.f, o11 = 0.f;
#pragma unroll
        for (int i = 0; i < 5; ++i) {
            int sa = j2 * 5 + i;
            int sb = i * 5 + k2;
            float a00 = __shfl_sync(FULLM, ac00, sa);
            float a01 = __shfl_sync(FULLM, ac01, sa);
            float a10 = __shfl_sync(FULLM, ac10, sa);
            float a11 = __shfl_sync(FULLM, ac11, sa);
            float b00 = __shfl_sync(FULLM, bc00, sb);
            float b01 = __shfl_sync(FULLM, bc01, sb);
            float b10 = __shfl_sync(FULLM, bc10, sb);
            float b11 = __shfl_sync(FULLM, bc11, sb);
            o00 = fmaf(a00, b00, o00); o00 = fmaf(a01, b10, o00);
            o01 = fmaf(a00, b01, o01); o01 = fmaf(a01, b11, o01);
            o10 = fmaf(a10, b00, o10); o10 = fmaf(a11, b10, o10);
            o11 = fmaf(a10, b01, o11); o11 = fmaf(a11, b11, o11);
        }
        ac00 = o00; ac01 = o01; ac10 = o10; ac11 = o11;
    }

    if (act) {
        *(float2*)(wres[warp] + r0 * 10 + c0)       = make_float2(ac00, ac01);
        *(float2*)(wres[warp] + (r0 + 1) * 10 + c0) = make_float2(ac10, ac11);
    }
    __syncthreads();

    // warp 0 merges: R = W0 @ W1 @ W2 @ W3 (time order)
    if (warp == 0) {
        float* cur = wres[0];
#pragma unroll
        for (int p = 1; p < 4; ++p) {
            const float* Bm = wres[p];
            float o00 = 0.f, o01 = 0.f, o10 = 0.f, o11 = 0.f;
#pragma unroll
            for (int i = 0; i < 10; i += 2) {
                float2 ar0 = *(const float2*)(cur + r0 * 10 + i);
                float2 ar1 = *(const float2*)(cur + (r0 + 1) * 10 + i);
                float2 b0  = *(const float2*)(Bm + i * 10 + c0);
                float2 b1  = *(const float2*)(Bm + (i + 1) * 10 + c0);
                o00 = fmaf(ar0.x, b0.x, o00); o00 = fmaf(ar0.y, b1.x, o00);
                o01 = fmaf(ar0.x, b0.y, o01); o01 = fmaf(ar0.y, b1.y, o01);
                o10 = fmaf(ar1.x, b0.x, o10); o10 = fmaf(ar1.y, b1.x, o10);
                o11 = fmaf(ar1.x, b0.y, o11); o11 = fmaf(ar1.y, b1.y, o11);
            }
            float* nxt = wk[p & 1];
            if (act) {
                *(float2*)(nxt + r0 * 10 + c0)       = make_float2(o00, o01);
                *(float2*)(nxt + (r0 + 1) * 10 + c0) = make_float2(o10, o11);
            }
            __syncwarp();
            cur = nxt;
        }
        float* o = out + (size_t)chain * 100;
        if (act) *(float4*)(o + lane * 4) = *(const float4*)(cur + lane * 4);
    }
}

extern "C" void kernel_launch(void* const* d_in, const int* in_sizes, int n_in,
                              void* d_out, int out_size) {
    const float* x = (const float*)d_in[0];
    const float* A = (const float*)d_in[1];
    if (n_in >= 2 && in_sizes[0] < in_sizes[1]) {
        const float* t = x; x = A; A = t;
    }

    step_kernel<<<NWARPS / WPB, 128>>>(x, A);       // 4096 blocks
    combine_kernel<<<NCHAIN, 128>>>((float*)d_out); // 128 blocks
}

// round 14
// speedup vs baseline: 1.1107x; 1.0721x over previous
#include <cuda_runtime.h>

#define N_B    64
#define T_LEN  2048
#define IN_D   8
#define C_CH   2
#define STEPS  2047
#define LCHUNK 8
#define NCHUNK 256           // 256*8 = 2048 >= 2047
#define WPB    4
#define NCHAIN (N_B * C_CH)          // 128
#define NPAIR  (NCHUNK / 2)          // 128 merged partials per chain
#define NWARPS (NCHAIN * NPAIR)      // 16384 warps, 2 adjacent chunks each
#define FULLM  0xffffffffu

__device__ __align__(16) float g_part[NCHAIN * NPAIR * 100];

// ---------------------------------------------------------------------------
// Kernel 1: one warp per (chain, chunk-pair). Each warp advances TWO ADJACENT
// 8-step chunks (2q, 2q+1), interleaved for ILP, then merges them in-register
// and writes one 16-step partial. Order-7 Taylor expm of skew G; tiles
// register-distributed (lane l<25 owns 2x2 tile (j2=l/5, k2=l%5)); exchanges
// via __shfl_sync. Steps past chain end use dx=0 => E=I exactly.
// ---------------------------------------------------------------------------
__global__ void __launch_bounds__(128) step_kernel(const float* __restrict__ x,
                                                   const float* __restrict__ A) {
    __shared__ float sk[C_CH * IN_D * 100];
    __shared__ float xs[WPB][2][(LCHUNK + 1) * IN_D];
    __shared__ __align__(16) float dxs[WPB][2][LCHUNK * IN_D];

    int tid = threadIdx.x;

    // skew = A - A^T
    for (int idx = tid; idx < C_CH * IN_D * 100; idx += 128) {
        int jk = idx % 100, ci = idx / 100;
        int j = jk / 10, k = jk % 10;
        sk[idx] = A[ci * 100 + j * 10 + k] - A[ci * 100 + k * 10 + j];
    }

    int warp = tid >> 5, lane = tid & 31;
    int w     = blockIdx.x * WPB + warp;     // [0, 16384)
    int q     = w & (NPAIR - 1);             // pair index
    int chain = w >> 7;
    int c     = chain & 1;
    int n     = chain >> 1;

    int t0j[2] = {(2 * q) * LCHUNK, (2 * q + 1) * LCHUNK};
    int nstepsj[2];
#pragma unroll
    for (int j = 0; j < 2; ++j) {
        nstepsj[j] = max(0, min(LCHUNK, STEPS - t0j[j]));
        const float* xp = x + ((size_t)n * T_LEN + t0j[j]) * IN_D;
        float* xw = xs[warp][j];
        int cnt = (nstepsj[j] + 1) * IN_D;
        for (int idx = lane; idx < cnt; idx += 32) xw[idx] = xp[idx];
    }
    __syncthreads();                          // sk + xw ready

#pragma unroll
    for (int j = 0; j < 2; ++j) {
        const float* xw = xs[warp][j];
        float* dxp = dxs[warp][j];
        int lim = nstepsj[j] * IN_D;
        for (int idx = lane; idx < LCHUNK * IN_D; idx += 32)
            dxp[idx] = (idx < lim) ? (xw[idx + IN_D] - xw[idx]) : 0.f;
    }
    __syncwarp();

    bool act = lane < 25;
    int l  = act ? lane : 24;
    int j2 = l / 5, k2 = l % 5;
    int r0 = 2 * j2, c0 = 2 * k2;
    float dI = (j2 == k2) ? 1.f : 0.f;

    // skew tiles -> registers (shared by both jobs: same chain/channel)
    const float* skc = sk + c * IN_D * 100;
    float ska[IN_D][4];
#pragma unroll
    for (int i = 0; i < IN_D; ++i) {
        float2 a0 = *(const float2*)(skc + i * 100 + r0 * 10 + c0);
        float2 a1 = *(const float2*)(skc + i * 100 + r0 * 10 + 10 + c0);
        ska[i][0] = a0.x; ska[i][1] = a0.y; ska[i][2] = a1.x; ska[i][3] = a1.y;
    }

    const float c2 = 0.5f,      c4 = 1.f / 24.f,  c6 = 1.f / 720.f;
    const float s2 = 1.f / 6.f, s4 = 1.f / 120.f, s6 = 1.f / 5040.f;

    float ac00[2], ac01[2], ac10[2], ac11[2];
#pragma unroll
    for (int j = 0; j < 2; ++j) { ac00[j] = dI; ac01[j] = 0.f; ac10[j] = 0.f; ac11[j] = dI; }

    float Gr0[2][10], Gr1[2][10], Wr0[2][10], Wr1[2][10];
    float g00[2], g01[2], g10[2], g11[2];
    float w00[2], w01[2], w10[2], w11[2];
    float C00[2], C01[2], C10[2], C11[2];
    float S00[2], S01[2], S10[2], S11[2];
    float e00[2], e01[2], e10[2], e11[2];

    for (int t = 0; t < LCHUNK; ++t) {
        // ---- G tiles ----
#pragma unroll
        for (int j = 0; j < 2; ++j) {
            const float* d = dxs[warp][j] + t * IN_D;
            float4 dA4 = *(const float4*)(d);
            float4 dB4 = *(const float4*)(d + 4);
            float dv[8] = {dA4.x, dA4.y, dA4.z, dA4.w, dB4.x, dB4.y, dB4.z, dB4.w};
            float a = 0.f, b = 0.f, cc = 0.f, dd = 0.f;
#pragma unroll
            for (int i = 0; i < 8; ++i) {
                a = fmaf(dv[i], ska[i][0], a); b  = fmaf(dv[i], ska[i][1], b);
                cc = fmaf(dv[i], ska[i][2], cc); dd = fmaf(dv[i], ska[i][3], dd);
            }
            g00[j] = a; g01[j] = b; g10[j] = cc; g11[j] = dd;
        }

        // ---- G strips ----
#pragma unroll
        for (int j = 0; j < 2; ++j)
#pragma unroll
            for (int k = 0; k < 5; ++k) {
                int src = j2 * 5 + k;
                Gr0[j][2*k]   = __shfl_sync(FULLM, g00[j], src);
                Gr0[j][2*k+1] = __shfl_sync(FULLM, g01[j], src);
                Gr1[j][2*k]   = __shfl_sync(FULLM, g10[j], src);
                Gr1[j][2*k+1] = __shfl_sync(FULLM, g11[j], src);
            }

        // ---- W = G@G ----
#pragma unroll
        for (int j = 0; j < 2; ++j) {
            float o00 = 0.f, o01 = 0.f, o10 = 0.f, o11 = 0.f;
#pragma unroll
            for (int i = 0; i < 5; ++i) {
                int src = i * 5 + k2;
                float b00 = __shfl_sync(FULLM, g00[j], src);
                float b01 = __shfl_sync(FULLM, g01[j], src);
                float b10 = __shfl_sync(FULLM, g10[j], src);
                float b11 = __shfl_sync(FULLM, g11[j], src);
                float a00 = Gr0[j][2*i], a01 = Gr0[j][2*i+1];
                float a10 = Gr1[j][2*i], a11 = Gr1[j][2*i+1];
                o00 = fmaf(a00, b00, o00); o00 = fmaf(a01, b10, o00);
                o01 = fmaf(a00, b01, o01); o01 = fmaf(a01, b11, o01);
                o10 = fmaf(a10, b00, o10); o10 = fmaf(a11, b10, o10);
                o11 = fmaf(a10, b01, o11); o11 = fmaf(a11, b11, o11);
            }
            w00[j] = o00; w01[j] = o01; w10[j] = o10; w11[j] = o11;
        }

        // ---- W strips ----
#pragma unroll
        for (int j = 0; j < 2; ++j)
#pragma unroll
            for (int k = 0; k < 5; ++k) {
                int src = j2 * 5 + k;
                Wr0[j][2*k]   = __shfl_sync(FULLM, w00[j], src);
                Wr0[j][2*k+1] = __shfl_sync(FULLM, w01[j], src);
                Wr1[j][2*k]   = __shfl_sync(FULLM, w10[j], src);
                Wr1[j][2*k+1] = __shfl_sync(FULLM, w11[j], src);
            }

        // ---- P = W@W ; C,S low-order folds ----
#pragma unroll
        for (int j = 0; j < 2; ++j) {
            float o00 = 0.f, o01 = 0.f, o10 = 0.f, o11 = 0.f;
#pragma unroll
            for (int i = 0; i < 5; ++i) {
                int src = i * 5 + k2;
                float b00 = __shfl_sync(FULLM, w00[j], src);
                float b01 = __shfl_sync(FULLM, w01[j], src);
                float b10 = __shfl_sync(FULLM, w10[j], src);
                float b11 = __shfl_sync(FULLM, w11[j], src);
                float a00 = Wr0[j][2*i], a01 = Wr0[j][2*i+1];
                float a10 = Wr1[j][2*i], a11 = Wr1[j][2*i+1];
                o00 = fmaf(a00, b00, o00); o00 = fmaf(a01, b10, o00);
                o01 = fmaf(a00, b01, o01); o01 = fmaf(a01, b11, o01);
                o10 = fmaf(a10, b00, o10); o10 = fmaf(a11, b10, o10);
                o11 = fmaf(a10, b01, o11); o11 = fmaf(a11, b11, o11);
            }
            C00[j] = fmaf(c4, o00, fmaf(c2, w00[j], dI));
            C01[j] = fmaf(c4, o01, c2 * w01[j]);
            C10[j] = fmaf(c4, o10, c2 * w10[j]);
            C11[j] = fmaf(c4, o11, fmaf(c2, w11[j], dI));
            S00[j] = fmaf(s4, o00, fmaf(s2, w00[j], dI));
            S01[j] = fmaf(s4, o01, s2 * w01[j]);
            S10[j] = fmaf(s4, o10, s2 * w10[j]);
            S11[j] = fmaf(s4, o11, fmaf(s2, w11[j], dI));
            // reuse g-regs to carry P tile for the V6 gather
            g00[j] = o00; g01[j] = o01; g10[j] = o10; g11[j] = o11;
        }

        // ---- V6 = W@P ; fold into C,S ----
#pragma unroll
        for (int j = 0; j < 2; ++j) {
            float o00 = 0.f, o01 = 0.f, o10 = 0.f, o11 = 0.f;
#pragma unroll
            for (int i = 0; i < 5; ++i) {
                int src = i * 5 + k2;
                float b00 = __shfl_sync(FULLM, g00[j], src);
                float b01 = __shfl_sync(FULLM, g01[j], src);
                float b10 = __shfl_sync(FULLM, g10[j], src);
                float b11 = __shfl_sync(FULLM, g11[j], src);
                float a00 = Wr0[j][2*i], a01 = Wr0[j][2*i+1];
                float a10 = Wr1[j][2*i], a11 = Wr1[j][2*i+1];
                o00 = fmaf(a00, b00, o00); o00 = fmaf(a01, b10, o00);
                o01 = fmaf(a00, b01, o01); o01 = fmaf(a01, b11, o01);
                o10 = fmaf(a10, b00, o10); o10 = fmaf(a11, b10, o10);
                o11 = fmaf(a10, b01, o11); o11 = fmaf(a11, b11, o11);
            }
            C00[j] = fmaf(c6, o00, C00[j]); C01[j] = fmaf(c6, o01, C01[j]);
            C10[j] = fmaf(c6, o10, C10[j]); C11[j] = fmaf(c6, o11, C11[j]);
            S00[j] = fmaf(s6, o00, S00[j]); S01[j] = fmaf(s6, o01, S01[j]);
            S10[j] = fmaf(s6, o10, S10[j]); S11[j] = fmaf(s6, o11, S11[j]);
        }

        // ---- E = C + G@S ----
#pragma unroll
        for (int j = 0; j < 2; ++j) {
            float o00 = C00[j], o01 = C01[j], o10 = C10[j], o11 = C11[j];
#pragma unroll
            for (int i = 0; i < 5; ++i) {
                int src = i * 5 + k2;
                float b00 = __shfl_sync(FULLM, S00[j], src);
                float b01 = __shfl_sync(FULLM, S01[j], src);
                float b10 = __shfl_sync(FULLM, S10[j], src);
                float b11 = __shfl_sync(FULLM, S11[j], src);
                float a00 = Gr0[j][2*i], a01 = Gr0[j][2*i+1];
                float a10 = Gr1[j][2*i], a11 = Gr1[j][2*i+1];
                o00 = fmaf(a00, b00, o00); o00 = fmaf(a01, b10, o00);
                o01 = fmaf(a00, b01, o01); o01 = fmaf(a01, b11, o01);
                o10 = fmaf(a10, b00, o10); o10 = fmaf(a11, b10, o10);
                o11 = fmaf(a10, b01, o11); o11 = fmaf(a11, b11, o11);
            }
            e00[j] = o00; e01[j] = o01; e10[j] = o10; e11[j] = o11;
        }

        // ---- Acc = Acc @ E ----
#pragma unroll
        for (int j = 0; j < 2; ++j) {
            float o00 = 0.f, o01 = 0.f, o10 = 0.f, o11 = 0.f;
#pragma unroll
            for (int i = 0; i < 5; ++i) {
                int sa = j2 * 5 + i;
                int sb = i * 5 + k2;
                float a00 = __shfl_sync(FULLM, ac00[j], sa);
                float a01 = __shfl_sync(FULLM, ac01[j], sa);
                float a10 = __shfl_sync(FULLM, ac10[j], sa);
                float a11 = __shfl_sync(FULLM, ac11[j], sa);
                float b00 = __shfl_sync(FULLM, e00[j], sb);
                float b01 = __shfl_sync(FULLM, e01[j], sb);
                float b10 = __shfl_sync(FULLM, e10[j], sb);
                float b11 = __shfl_sync(FULLM, e11[j], sb);
                o00 = fmaf(a00, b00, o00); o00 = fmaf(a01, b10, o00);
                o01 = fmaf(a00, b01, o01); o01 = fmaf(a01, b11, o01);
                o10 = fmaf(a10, b00, o10); o10 = fmaf(a11, b10, o10);
                o11 = fmaf(a10, b01, o11); o11 = fmaf(a11, b11, o11);
            }
            ac00[j] = o00; ac01[j] = o01; ac10[j] = o10; ac11[j] = o11;
        }
    }

    // ---- merge the adjacent pair: M = Acc0 @ Acc1 (time order) ----
    {
        float o00 = 0.f, o01 = 0.f, o10 = 0.f, o11 = 0.f;
#pragma unroll
        for (int i = 0; i < 5; ++i) {
            int sa = j2 * 5 + i;
            int sb = i * 5 + k2;
            float a00 = __shfl_sync(FULLM, ac00[0], sa);
            float a01 = __shfl_sync(FULLM, ac01[0], sa);
            float a10 = __shfl_sync(FULLM, ac10[0], sa);
            float a11 = __shfl_sync(FULLM, ac11[0], sa);
            float b00 = __shfl_sync(FULLM, ac00[1], sb);
            float b01 = __shfl_sync(FULLM, ac01[1], sb);
            float b10 = __shfl_sync(FULLM, ac10[1], sb);
            float b11 = __shfl_sync(FULLM, ac11[1], sb);
            o00 = fmaf(a00, b00, o00); o00 = fmaf(a01, b10, o00);
            o01 = fmaf(a00, b01, o01); o01 = fmaf(a01, b11, o01);
            o10 = fmaf(a10, b00, o10); o10 = fmaf(a11, b10, o10);
            o11 = fmaf(a10, b01, o11); o11 = fmaf(a11, b11, o11);
        }
        if (act) {
            float* pp = g_part + (size_t)(chain * NPAIR + q) * 100;
            *(float2*)(pp + r0 * 10 + c0)       = make_float2(o00, o01);
            *(float2*)(pp + (r0 + 1) * 10 + c0) = make_float2(o10, o11);
        }
    }
}

// ---------------------------------------------------------------------------
// Combine: one block per chain, 16 warps per block. Each warp serially
// reduces 8 consecutive partials (register-shuffle matmuls); the 16 warp
// results are merged by a 4-level binary tree in shared memory.
// 2048 warps total -> latency hidden by co-residency; log-depth tail.
// ---------------------------------------------------------------------------
__global__ void __launch_bounds__(512) combine_kernel(float* __restrict__ out) {
    __shared__ __align__(16) float sm[16][100];

    int chain = blockIdx.x;
    int warp = threadIdx.x >> 5, lane = threadIdx.x & 31;
    bool act = lane < 25;
    int l  = act ? lane : 24;
    int j2 = l / 5, k2 = l % 5;
    int r0 = 2 * j2, c0 = 2 * k2;

    // ---- Phase 1: each warp reduces 8 consecutive partials ----
    const float* src = g_part + ((size_t)chain * NPAIR + warp * 8) * 100;

    float2 a0 = *(const float2*)(src + r0 * 10 + c0);
    float2 a1 = *(const float2*)(src + (r0 + 1) * 10 + c0);
    float ac00 = a0.x, ac01 = a0.y, ac10 = a1.x, ac11 = a1.y;

    // simple 1-deep software pipeline on the loads
    float2 n0 = *(const float2*)(src + 100 + r0 * 10 + c0);
    float2 n1 = *(const float2*)(src + 100 + (r0 + 1) * 10 + c0);

    for (int p = 1; p < 8; ++p) {
        float bc00 = n0.x, bc01 = n0.y, bc10 = n1.x, bc11 = n1.y;
        if (p < 7) {
            n0 = *(const float2*)(src + (p + 1) * 100 + r0 * 10 + c0);
            n1 = *(const float2*)(src + (p + 1) * 100 + (r0 + 1) * 10 + c0);
        }
        float o00 = 0.f, o01 = 0.f, o10 = 0.f, o11 = 0.f;
#pragma unroll
        for (int i = 0; i < 5; ++i) {
            int sa = j2 * 5 + i;
            int sb = i * 5 + k2;
            float a00 = __shfl_sync(FULLM, ac00, sa);
            float a01 = __shfl_sync(FULLM, ac01, sa);
            float a10 = __shfl_sync(FULLM, ac10, sa);
            float a11 = __shfl_sync(FULLM, ac11, sa);
            float b00 = __shfl_sync(FULLM, bc00, sb);
            float b01 = __shfl_sync(FULLM, bc01, sb);
            float b10 = __shfl_sync(FULLM, bc10, sb);
            float b11 = __shfl_sync(FULLM, bc11, sb);
            o00 = fmaf(a00, b00, o00); o00 = fmaf(a01, b10, o00);
            o01 = fmaf(a00, b01, o01); o01 = fmaf(a01, b11, o01);
            o10 = fmaf(a10, b00, o10); o10 = fmaf(a11, b10, o10);
            o11 = fmaf(a10, b01, o11); o11 = fmaf(a11, b11, o11);
        }
        ac00 = o00; ac01 = o01; ac10 = o10; ac11 = o11;
    }

    if (act) {
        *(float2*)(sm[warp] + r0 * 10 + c0)       = make_float2(ac00, ac01);
        *(float2*)(sm[warp] + (r0 + 1) * 10 + c0) = make_float2(ac10, ac11);
    }

    // ---- Phase 2: binary tree over 16 warp results (time order) ----
    for (int lvl = 8; lvl >= 1; lvl >>= 1) {
        __syncthreads();
        if (warp < lvl) {
            const float* Am = sm[2 * warp];
            const float* Bm = sm[2 * warp + 1];
            float2 ta0 = *(const float2*)(Am + r0 * 10 + c0);
            float2 ta1 = *(const float2*)(Am + (r0 + 1) * 10 + c0);
            float2 tb0 = *(const float2*)(Bm + r0 * 10 + c0);
            float2 tb1 = *(const float2*)(Bm + (r0 + 1) * 10 + c0);
            float o00 = 0.f, o01 = 0.f, o10 = 0.f, o11 = 0.f;
#pragma unroll
            for (int i = 0; i < 5; ++i) {
                int sa = j2 * 5 + i;
                int sb = i * 5 + k2;
                float a00 = __shfl_sync(FULLM, ta0.x, sa);
                float a01 = __shfl_sync(FULLM, ta0.y, sa);
                float a10 = __shfl_sync(FULLM, ta1.x, sa);
                float a11 = __shfl_sync(FULLM, ta1.y, sa);
                float b00 = __shfl_sync(FULLM, tb0.x, sb);
                float b01 = __shfl_sync(FULLM, tb0.y, sb);
                float b10 = __shfl_sync(FULLM, tb1.x, sb);
                float b11 = __shfl_sync(FULLM, tb1.y, sb);
                o00 = fmaf(a00, b00, o00); o00 = fmaf(a01, b10, o00);
                o01 = fmaf(a00, b01, o01); o01 = fmaf(a01, b11, o01);
                o10 = fmaf(a10, b00, o10); o10 = fmaf(a11, b10, o10);
                o11 = fmaf(a10, b01, o11); o11 = fmaf(a11, b11, o11);
            }
            __syncwarp();   // all reads of sm[2w],[2w+1] done before write to sm[w]
            if (act) {
                *(float2*)(sm[warp] + r0 * 10 + c0)       = make_float2(o00, o01);
                *(float2*)(sm[warp] + (r0 + 1) * 10 + c0) = make_float2(o10, o11);
            }
        }
    }
    __syncthreads();

    if (warp == 0 && act) {
        float* o = out + (size_t)chain * 100;
        *(float4*)(o + lane * 4) = *(const float4*)(sm[0] + lane * 4);
    }
}

extern "C" void kernel_launch(void* const* d_in, const int* in_sizes, int n_in,
                              void* d_out, int out_size) {
    const float* x = (const float*)d_in[0];
    const float* A = (const float*)d_in[1];
    if (n_in >= 2 && in_sizes[0] < in_sizes[1]) {
        const float* t = x; x = A; A = t;
    }

    step_kernel<<<NWARPS / WPB, 128>>>(x, A);       // 4096 blocks
    combine_kernel<<<NCHAIN, 512>>>((float*)d_out); // 128 blocks x 16 warps
}